// round 7
// baseline (speedup 1.0000x reference)
#include <cuda_runtime.h>

#define BB 8
#define CC 64
#define HH 64
#define WW 64
#define NROI 4096
#define NPER 512   // rois per batch-outer index
#define CLAMPB 50  // 64 - 14: window base clamp so base+13 <= 63

// NHWC scratch copy of the feature map (8 MB), float4-aligned.
__device__ float4 g_featT4[BB * HH * WW * (CC / 4)];

// Antiderivative of the bilinear tent kernel max(0, 1-|t|), clipped.
__device__ __forceinline__ float tentI(float t) {
    t = fminf(1.0f, fmaxf(-1.0f, t));
    float a = t + 1.0f;
    float b = 1.0f - t;
    return (t < 0.0f) ? 0.5f * a * a : 1.0f - 0.5f * b * b;
}

// NCHW -> NHWC transpose, one 64(c)x64(x) tile per (b,y).
// float4 loads along x, float4 stores along c. 512 blocks x 256 threads.
__global__ __launch_bounds__(256) void transpose_nchw_nhwc(const float* __restrict__ feat) {
    __shared__ float tile[64][65];   // tile[x][c]
    int by = blockIdx.x;             // b*HH + y
    int b  = by >> 6;
    int y  = by & 63;
    int t  = threadIdx.x;

    int cRow = t >> 4;               // 0..15
    int x4   = (t & 15) << 2;        // 0,4,...,60
#pragma unroll
    for (int k = 0; k < 4; ++k) {
        int c = cRow + (k << 4);
        float4 v = *(const float4*)(feat + (((b * CC + c) * HH + y) * WW) + x4);
        tile[x4 + 0][c] = v.x;
        tile[x4 + 1][c] = v.y;
        tile[x4 + 2][c] = v.z;
        tile[x4 + 3][c] = v.w;
    }
    __syncthreads();

    int xRow = t >> 4;
    int c4   = (t & 15) << 2;
    float* dst = (float*)g_featT4;
#pragma unroll
    for (int k = 0; k < 4; ++k) {
        int x = xRow + (k << 4);
        float4 v = make_float4(tile[x][c4 + 0], tile[x][c4 + 1],
                               tile[x][c4 + 2], tile[x][c4 + 3]);
        *(float4*)(dst + ((size_t)(by * WW + x) * CC) + c4) = v;
    }
}

// 4 warps (128 lanes) per roi: 16 channel-lanes (float4) x 8-way y-split,
// 2 rows per thread (j = hg, hg+8) fused into ONE unrolled loop so both
// rows' loads are in flight together. Row 1 unconditional (weights are
// exactly 0 outside the box; clamped window keeps loads in-bounds).
// 256-thread block = 2 rois. Grid = NROI/2 = 2048 blocks.
__global__ __launch_bounds__(256, 4) void proi_kernel(const float* __restrict__ rois,
                                                      float* __restrict__ out) {
    __shared__ float  wxs[2][16];
    __shared__ float  wys[2][16];
    __shared__ float  inva[2];
    __shared__ float4 partial[8][16];

    int tid   = threadIdx.x;
    int lane  = tid & 31;
    int warp  = tid >> 5;
    int roiIB = warp >> 2;              // roi within block: 0..1
    int wIR   = warp & 3;               // warp within roi: 0..3
    int li    = lane & 15;              // channel-group lane (c = 4*li..4*li+3)
    int half  = lane >> 4;
    int hg    = (wIR << 1) + half;      // y-phase 0..7

    int r = (blockIdx.x << 1) + roiIB;
    // output row r <-> roi storage (n*B + b_out), r = b_out*512 + n
    int b_out = r >> 9;
    int n     = r & (NPER - 1);
    const float* rp = rois + (n * BB + b_out) * 5;

    int   bidx = (int)__ldg(rp + 0);
    float x1   = __ldg(rp + 1);
    float y1   = __ldg(rp + 2);
    float x2   = __ldg(rp + 3);
    float y2   = __ldg(rp + 4);

    // Clamped 14-wide windows: tent weights outside the true box are exactly 0,
    // and base+13 <= 63 keeps every load in-bounds.
    int ix0 = min((int)floorf(x1), CLAMPB);   // x1 >= 0
    int iy0 = min((int)floorf(y1), CLAMPB);
    int ix1 = min(WW - 1, (int)ceilf(x2));
    int iy1 = min(HH - 1, (int)ceilf(y2));
    int nxW = ix1 - ix0 + 1;            // 5..14, uniform per roi
    int nyW = iy1 - iy0 + 1;            // 5..14, uniform per roi

    // One warp per roi computes the weights: lanes 0-15 -> wx, 16-31 -> wy.
    if (wIR == 0) {
        float lo   = (half == 0) ? x1 : y1;
        float hi   = (half == 0) ? x2 : y2;
        int   base = (half == 0) ? ix0 : iy0;
        float fi   = (float)(base + li);
        float w    = tentI(hi - fi) - tentI(lo - fi);
        if (half == 0) wxs[roiIB][li] = w;
        else           wys[roiIB][li] = w;
        if (lane == 0)
            inva[roiIB] = 1.0f / ((x2 - x1) * (y2 - y1));
    }
    __syncthreads();

    const float4* fbase = g_featT4 + (((bidx * HH + iy0) * WW + ix0) << 4) + li;

    float wy1 = wys[roiIB][hg];         // 0 beyond box
    float wy2 = wys[roiIB][hg + 8];     // hg+8 <= 15, 0 beyond box
    bool  act2 = (hg + 8) < nyW;        // only to save traffic

    const float4* p1 = fbase + (hg * WW << 4);
    const float4* p2 = fbase + ((hg + 8) * WW << 4);   // in-bounds (clamp)

    float4 r1 = make_float4(0.f, 0.f, 0.f, 0.f);
    float4 r2 = make_float4(0.f, 0.f, 0.f, 0.f);

#pragma unroll
    for (int ii = 0; ii < 14; ++ii) {
        if (ii < nxW) {
            float w  = wxs[roiIB][ii];
            float4 v1 = p1[ii << 4];
            r1.x = fmaf(w, v1.x, r1.x);
            r1.y = fmaf(w, v1.y, r1.y);
            r1.z = fmaf(w, v1.z, r1.z);
            r1.w = fmaf(w, v1.w, r1.w);
            if (act2) {
                float4 v2 = p2[ii << 4];
                r2.x = fmaf(w, v2.x, r2.x);
                r2.y = fmaf(w, v2.y, r2.y);
                r2.z = fmaf(w, v2.z, r2.z);
                r2.w = fmaf(w, v2.w, r2.w);
            }
        }
    }

    float4 acc;
    acc.x = fmaf(wy1, r1.x, wy2 * r2.x);
    acc.y = fmaf(wy1, r1.y, wy2 * r2.y);
    acc.z = fmaf(wy1, r1.z, wy2 * r2.z);
    acc.w = fmaf(wy1, r1.w, wy2 * r2.w);

    // Combine the two halves of this warp.
    acc.x += __shfl_xor_sync(0xFFFFFFFFu, acc.x, 16, 32);
    acc.y += __shfl_xor_sync(0xFFFFFFFFu, acc.y, 16, 32);
    acc.z += __shfl_xor_sync(0xFFFFFFFFu, acc.z, 16, 32);
    acc.w += __shfl_xor_sync(0xFFFFFFFFu, acc.w, 16, 32);

    if (half == 0) partial[warp][li] = acc;
    __syncthreads();

    // Final combine across the 4 warps of each roi; 32 threads write 2 rois.
    if (tid < 32) {
        int rid = tid >> 4;
        int l   = tid & 15;
        float4 a = partial[(rid << 2) + 0][l];
        float4 b = partial[(rid << 2) + 1][l];
        float4 c = partial[(rid << 2) + 2][l];
        float4 d = partial[(rid << 2) + 3][l];
        float ia = inva[rid];
        float4 o = make_float4((a.x + b.x + c.x + d.x) * ia,
                               (a.y + b.y + c.y + d.y) * ia,
                               (a.z + b.z + c.z + d.z) * ia,
                               (a.w + b.w + c.w + d.w) * ia);
        int rr = (blockIdx.x << 1) + rid;
        ((float4*)out)[(rr << 4) + l] = o;
    }
}

extern "C" void kernel_launch(void* const* d_in, const int* in_sizes, int n_in,
                              void* d_out, int out_size) {
    const float* feature = (const float*)d_in[0];
    const float* rois    = (const float*)d_in[1];
    float* out           = (float*)d_out;

    transpose_nchw_nhwc<<<BB * HH, 256>>>(feature);
    proi_kernel<<<NROI / 2, 256>>>(rois, out);
}

// round 8
// speedup vs baseline: 1.0085x; 1.0085x over previous
#include <cuda_runtime.h>

#define BB 8
#define CC 64
#define HH 64
#define WW 64
#define NROI 4096
#define NPER 512   // rois per batch-outer index
#define CLAMPB 50  // 64 - 14: window base clamp so base+13 <= 63

// NHWC scratch copy of the feature map (8 MB), float4-aligned.
__device__ float4 g_featT4[BB * HH * WW * (CC / 4)];

// Antiderivative of the bilinear tent kernel max(0, 1-|t|), clipped.
__device__ __forceinline__ float tentI(float t) {
    t = fminf(1.0f, fmaxf(-1.0f, t));
    float a = t + 1.0f;
    float b = 1.0f - t;
    return (t < 0.0f) ? 0.5f * a * a : 1.0f - 0.5f * b * b;
}

// NCHW -> NHWC transpose, one 64(c)x64(x) tile per (b,y).
// float4 loads along x, float4 stores along c. 512 blocks x 256 threads.
__global__ __launch_bounds__(256) void transpose_nchw_nhwc(const float* __restrict__ feat) {
    __shared__ float tile[64][65];   // tile[x][c]
    int by = blockIdx.x;             // b*HH + y
    int b  = by >> 6;
    int y  = by & 63;
    int t  = threadIdx.x;

    int cRow = t >> 4;               // 0..15
    int x4   = (t & 15) << 2;        // 0,4,...,60
#pragma unroll
    for (int k = 0; k < 4; ++k) {
        int c = cRow + (k << 4);
        float4 v = *(const float4*)(feat + (((b * CC + c) * HH + y) * WW) + x4);
        tile[x4 + 0][c] = v.x;
        tile[x4 + 1][c] = v.y;
        tile[x4 + 2][c] = v.z;
        tile[x4 + 3][c] = v.w;
    }
    __syncthreads();

    int xRow = t >> 4;
    int c4   = (t & 15) << 2;
    float* dst = (float*)g_featT4;
#pragma unroll
    for (int k = 0; k < 4; ++k) {
        int x = xRow + (k << 4);
        float4 v = make_float4(tile[x][c4 + 0], tile[x][c4 + 1],
                               tile[x][c4 + 2], tile[x][c4 + 3]);
        *(float4*)(dst + ((size_t)(by * WW + x) * CC) + c4) = v;
    }
}

// 4 warps (128 lanes) per roi: 16 channel-lanes (float4) x 8-way y-split,
// 2 rows per thread (j = hg, hg+8) in two straight-line blocks.
// Loads are UNCONDITIONAL over all 14 taps: tent weights outside the true
// box are exactly 0 and the clamped window keeps every address in-bounds,
// so ptxas can front-batch the whole load stream (no predicates).
// 256-thread block = 2 rois. Grid = NROI/2 = 2048 blocks.
__global__ __launch_bounds__(256, 4) void proi_kernel(const float* __restrict__ rois,
                                                      float* __restrict__ out) {
    __shared__ float  wxs[2][16];
    __shared__ float  wys[2][16];
    __shared__ float  inva[2];
    __shared__ float4 partial[8][16];

    int tid   = threadIdx.x;
    int lane  = tid & 31;
    int warp  = tid >> 5;
    int roiIB = warp >> 2;              // roi within block: 0..1
    int wIR   = warp & 3;               // warp within roi: 0..3
    int li    = lane & 15;              // channel-group lane (c = 4*li..4*li+3)
    int half  = lane >> 4;
    int hg    = (wIR << 1) + half;      // y-phase 0..7

    int r = (blockIdx.x << 1) + roiIB;
    // output row r <-> roi storage (n*B + b_out), r = b_out*512 + n
    int b_out = r >> 9;
    int n     = r & (NPER - 1);
    const float* rp = rois + (n * BB + b_out) * 5;

    int   bidx = (int)__ldg(rp + 0);
    float x1   = __ldg(rp + 1);
    float y1   = __ldg(rp + 2);
    float x2   = __ldg(rp + 3);
    float y2   = __ldg(rp + 4);

    // Clamped 14-wide windows.
    int ix0 = min((int)floorf(x1), CLAMPB);   // x1 >= 0
    int iy0 = min((int)floorf(y1), CLAMPB);
    int iy1 = min(HH - 1, (int)ceilf(y2));
    int nyW = iy1 - iy0 + 1;            // 5..14, uniform per roi

    // One warp per roi computes the weights: lanes 0-15 -> wx, 16-31 -> wy.
    if (wIR == 0) {
        float lo   = (half == 0) ? x1 : y1;
        float hi   = (half == 0) ? x2 : y2;
        int   base = (half == 0) ? ix0 : iy0;
        float fi   = (float)(base + li);
        float w    = tentI(hi - fi) - tentI(lo - fi);
        if (half == 0) wxs[roiIB][li] = w;
        else           wys[roiIB][li] = w;
        if (lane == 0)
            inva[roiIB] = 1.0f / ((x2 - x1) * (y2 - y1));
    }
    __syncthreads();

    const float4* fbase = g_featT4 + (((bidx * HH + iy0) * WW + ix0) << 4) + li;

    float4 acc = make_float4(0.f, 0.f, 0.f, 0.f);

    // Row 1: j = hg. Unconditional (wy = 0 beyond the box).
    {
        float wy = wys[roiIB][hg];
        const float4* fp = fbase + (hg * WW << 4);
        float4 racc = make_float4(0.f, 0.f, 0.f, 0.f);
#pragma unroll
        for (int ii = 0; ii < 14; ++ii) {
            float4 v = fp[ii << 4];
            float  w = wxs[roiIB][ii];
            racc.x = fmaf(w, v.x, racc.x);
            racc.y = fmaf(w, v.y, racc.y);
            racc.z = fmaf(w, v.z, racc.z);
            racc.w = fmaf(w, v.w, racc.w);
        }
        acc.x = wy * racc.x;
        acc.y = wy * racc.y;
        acc.z = wy * racc.z;
        acc.w = wy * racc.w;
    }

    // Row 2: j = hg + 8. Whole block skipped uniformly when beyond the box.
    if (hg + 8 < nyW) {
        float wy = wys[roiIB][hg + 8];
        const float4* fp = fbase + ((hg + 8) * WW << 4);
        float4 racc = make_float4(0.f, 0.f, 0.f, 0.f);
#pragma unroll
        for (int ii = 0; ii < 14; ++ii) {
            float4 v = fp[ii << 4];
            float  w = wxs[roiIB][ii];
            racc.x = fmaf(w, v.x, racc.x);
            racc.y = fmaf(w, v.y, racc.y);
            racc.z = fmaf(w, v.z, racc.z);
            racc.w = fmaf(w, v.w, racc.w);
        }
        acc.x = fmaf(wy, racc.x, acc.x);
        acc.y = fmaf(wy, racc.y, acc.y);
        acc.z = fmaf(wy, racc.z, acc.z);
        acc.w = fmaf(wy, racc.w, acc.w);
    }

    // Combine the two halves of this warp.
    acc.x += __shfl_xor_sync(0xFFFFFFFFu, acc.x, 16, 32);
    acc.y += __shfl_xor_sync(0xFFFFFFFFu, acc.y, 16, 32);
    acc.z += __shfl_xor_sync(0xFFFFFFFFu, acc.z, 16, 32);
    acc.w += __shfl_xor_sync(0xFFFFFFFFu, acc.w, 16, 32);

    if (half == 0) partial[warp][li] = acc;
    __syncthreads();

    // Final combine across the 4 warps of each roi; 32 threads write 2 rois.
    if (tid < 32) {
        int rid = tid >> 4;
        int l   = tid & 15;
        float4 a = partial[(rid << 2) + 0][l];
        float4 b = partial[(rid << 2) + 1][l];
        float4 c = partial[(rid << 2) + 2][l];
        float4 d = partial[(rid << 2) + 3][l];
        float ia = inva[rid];
        float4 o = make_float4((a.x + b.x + c.x + d.x) * ia,
                               (a.y + b.y + c.y + d.y) * ia,
                               (a.z + b.z + c.z + d.z) * ia,
                               (a.w + b.w + c.w + d.w) * ia);
        int rr = (blockIdx.x << 1) + rid;
        ((float4*)out)[(rr << 4) + l] = o;
    }
}

extern "C" void kernel_launch(void* const* d_in, const int* in_sizes, int n_in,
                              void* d_out, int out_size) {
    const float* feature = (const float*)d_in[0];
    const float* rois    = (const float*)d_in[1];
    float* out           = (float*)d_out;

    transpose_nchw_nhwc<<<BB * HH, 256>>>(feature);
    proi_kernel<<<NROI / 2, 256>>>(rois, out);
}

// round 10
// speedup vs baseline: 1.1915x; 1.1815x over previous
#include <cuda_runtime.h>
#include <cuda_fp16.h>

#define BB 8
#define CC 64
#define HH 64
#define WW 64
#define NROI 4096
#define NPER 512   // rois per batch-outer index
#define CLAMPB 50  // 64 - 14: window base clamp so base+13 <= 63

// NHWC fp16 scratch copy of the feature map (4 MB), 16B-aligned.
__device__ __align__(16) __half g_featH[BB * HH * WW * CC];

__device__ __forceinline__ unsigned h2_bits(__half2 h) {
    return *reinterpret_cast<unsigned*>(&h);
}
__device__ __forceinline__ __half2 bits_h2(unsigned u) {
    return *reinterpret_cast<__half2*>(&u);
}

// Antiderivative of the bilinear tent kernel max(0, 1-|t|), clipped.
__device__ __forceinline__ float tentI(float t) {
    t = fminf(1.0f, fmaxf(-1.0f, t));
    float a = t + 1.0f;
    float b = 1.0f - t;
    return (t < 0.0f) ? 0.5f * a * a : 1.0f - 0.5f * b * b;
}

// NCHW fp32 -> NHWC fp16 transpose, one 64(c)x64(x) tile per (b,y).
// float4 loads along x; uint4 (8 half) stores along c. 512 blocks x 256 threads.
__global__ __launch_bounds__(256) void transpose_nchw_nhwc(const float* __restrict__ feat) {
    __shared__ float tile[64][65];   // tile[x][c]
    int by = blockIdx.x;             // b*HH + y
    int b  = by >> 6;
    int y  = by & 63;
    int t  = threadIdx.x;

    int cRow = t >> 4;               // 0..15
    int x4   = (t & 15) << 2;        // 0,4,...,60
#pragma unroll
    for (int k = 0; k < 4; ++k) {
        int c = cRow + (k << 4);
        float4 v = *(const float4*)(feat + (((b * CC + c) * HH + y) * WW) + x4);
        tile[x4 + 0][c] = v.x;
        tile[x4 + 1][c] = v.y;
        tile[x4 + 2][c] = v.z;
        tile[x4 + 3][c] = v.w;
    }
    __syncthreads();

    int xr = t >> 3;                 // 0..31
    int cg = (t & 7) << 3;           // 0,8,...,56
#pragma unroll
    for (int k = 0; k < 2; ++k) {
        int x = xr + (k << 5);
        __half2 h0 = __floats2half2_rn(tile[x][cg + 0], tile[x][cg + 1]);
        __half2 h1 = __floats2half2_rn(tile[x][cg + 2], tile[x][cg + 3]);
        __half2 h2 = __floats2half2_rn(tile[x][cg + 4], tile[x][cg + 5]);
        __half2 h3 = __floats2half2_rn(tile[x][cg + 6], tile[x][cg + 7]);
        uint4 o;
        o.x = h2_bits(h0);  o.y = h2_bits(h1);
        o.z = h2_bits(h2);  o.w = h2_bits(h3);
        *(uint4*)(g_featH + ((size_t)(by * WW + x) * CC) + cg) = o;
    }
}

// 4 warps (128 lanes) per roi: 8 channel-lanes (uint4 = 8 fp16) x 16 y-phases,
// 1 row per thread. Row-guard is a single divergent branch; tap predicates are
// warp-uniform (R6 structure). fp32 accumulation.
// 256-thread block = 2 rois. Grid = NROI/2 = 2048 blocks.
__global__ __launch_bounds__(256, 4) void proi_kernel(const float* __restrict__ rois,
                                                      float* __restrict__ out) {
    __shared__ float wxs[2][16];
    __shared__ float wys[2][16];
    __shared__ float inva[2];
    __shared__ float partial[2][4][64];

    int tid   = threadIdx.x;
    int lane  = tid & 31;
    int warp  = tid >> 5;
    int roiIB = warp >> 2;              // roi within block: 0..1
    int wIR   = warp & 3;               // warp within roi: 0..3
    int li    = lane & 7;               // channel-group lane (c = 8*li..8*li+7)
    int pgrp  = lane >> 3;              // 0..3
    int phase = (wIR << 2) + pgrp;      // y-row 0..15 (14,15 always idle)

    int r = (blockIdx.x << 1) + roiIB;
    // output row r <-> roi storage (n*B + b_out), r = b_out*512 + n
    int b_out = r >> 9;
    int n     = r & (NPER - 1);
    const float* rp = rois + (n * BB + b_out) * 5;

    int   bidx = (int)__ldg(rp + 0);
    float x1   = __ldg(rp + 1);
    float y1   = __ldg(rp + 2);
    float x2   = __ldg(rp + 3);
    float y2   = __ldg(rp + 4);

    // Clamped 14-wide windows: tent weights outside the true box are exactly 0,
    // and base+13 <= 63 keeps guarded accesses in-bounds.
    int ix0 = min((int)floorf(x1), CLAMPB);   // x1 >= 0
    int iy0 = min((int)floorf(y1), CLAMPB);
    int ix1 = min(WW - 1, (int)ceilf(x2));
    int iy1 = min(HH - 1, (int)ceilf(y2));
    int nxW = ix1 - ix0 + 1;            // 5..14, uniform per roi
    int nyW = iy1 - iy0 + 1;            // 5..14, uniform per roi

    // One warp per roi computes the weights: lanes 0-15 -> wx, 16-31 -> wy.
    if (wIR == 0) {
        int  hw    = lane >> 4;
        int  wl    = lane & 15;
        float lo   = (hw == 0) ? x1 : y1;
        float hi   = (hw == 0) ? x2 : y2;
        int   base = (hw == 0) ? ix0 : iy0;
        float fi   = (float)(base + wl);
        float w    = tentI(hi - fi) - tentI(lo - fi);
        if (hw == 0) wxs[roiIB][wl] = w;
        else         wys[roiIB][wl] = w;
        if (lane == 0)
            inva[roiIB] = 1.0f / ((x2 - x1) * (y2 - y1));
    }
    __syncthreads();

    float acc[8];
#pragma unroll
    for (int c = 0; c < 8; ++c) acc[c] = 0.0f;

    if (phase < nyW) {
        float wy = wys[roiIB][phase];
        const uint4* p = (const uint4*)(g_featH
            + ((size_t)((bidx * HH + iy0 + phase) * WW + ix0) * CC) + (li << 3));
#pragma unroll
        for (int ii = 0; ii < 14; ++ii) {
            if (ii < nxW) {             // warp-uniform predicate
                uint4 v = p[ii << 3];   // tap stride = 128 B = 8 uint4
                float w = wxs[roiIB][ii];
                float2 f0 = __half22float2(bits_h2(v.x));
                float2 f1 = __half22float2(bits_h2(v.y));
                float2 f2 = __half22float2(bits_h2(v.z));
                float2 f3 = __half22float2(bits_h2(v.w));
                acc[0] = fmaf(w, f0.x, acc[0]);
                acc[1] = fmaf(w, f0.y, acc[1]);
                acc[2] = fmaf(w, f1.x, acc[2]);
                acc[3] = fmaf(w, f1.y, acc[3]);
                acc[4] = fmaf(w, f2.x, acc[4]);
                acc[5] = fmaf(w, f2.y, acc[5]);
                acc[6] = fmaf(w, f3.x, acc[6]);
                acc[7] = fmaf(w, f3.y, acc[7]);
            }
        }
#pragma unroll
        for (int c = 0; c < 8; ++c) acc[c] *= wy;
    }

    // Reduce over the 4 phase-groups within the warp.
#pragma unroll
    for (int c = 0; c < 8; ++c) {
        acc[c] += __shfl_xor_sync(0xFFFFFFFFu, acc[c], 8, 32);
        acc[c] += __shfl_xor_sync(0xFFFFFFFFu, acc[c], 16, 32);
    }

    if (lane < 8) {
        float* dst = &partial[roiIB][wIR][lane << 3];
#pragma unroll
        for (int c = 0; c < 8; ++c) dst[c] = acc[c];
    }
    __syncthreads();

    // Final combine across the 4 warps of each roi; 128 threads write 2 rois.
    if (tid < 128) {
        int rid = tid >> 6;
        int c   = tid & 63;
        float s = partial[rid][0][c] + partial[rid][1][c]
                + partial[rid][2][c] + partial[rid][3][c];
        int rr = (blockIdx.x << 1) + rid;
        out[(rr << 6) + c] = s * inva[rid];
    }
}

extern "C" void kernel_launch(void* const* d_in, const int* in_sizes, int n_in,
                              void* d_out, int out_size) {
    const float* feature = (const float*)d_in[0];
    const float* rois    = (const float*)d_in[1];
    float* out           = (float*)d_out;

    transpose_nchw_nhwc<<<BB * HH, 256>>>(feature);
    proi_kernel<<<NROI / 2, 256>>>(rois, out);
}